// round 14
// baseline (speedup 1.0000x reference)
#include <cuda_runtime.h>
#include <cuda_bf16.h>
#include <cstddef>
#include <cstdint>

#define ASTR 272u
#define AH0 0u
#define AL0 34816u
#define AH1 69632u
#define AL1 104448u
#define GO  139264u
#define GSTR 132
#define DSMEM 206848
#define NT 512

// fragment-ordered bf16 weight planes, 7 (hi,lo) pairs of 32KB tiles:
// p0: W1 k0-127 @0 ; p1: W1 k128-255 @65536 ; p2: W2 @131072 ;
// p3-6: W3 n-chunk nc @196608+nc*65536   (lo plane = hi + 32768)
__device__ __align__(1024) unsigned char g_wsc[458752];

__device__ __forceinline__ uint32_t su32(const void* p) {
    uint32_t a;
    asm("{ .reg .u64 t; cvta.to.shared.u64 t, %1; cvt.u32.u64 %0, t; }" : "=r"(a) : "l"(p));
    return a;
}
__device__ __forceinline__ void bsplit(float v, __nv_bfloat16& h, __nv_bfloat16& l) {
    h = __float2bfloat16(v);
    l = __float2bfloat16(v - __bfloat162float(h));
}
__device__ __forceinline__ void pk2hl(float a, float b, uint32_t& hi, uint32_t& lo) {
    __nv_bfloat16 ha, la, hb, lb;
    bsplit(a, ha, la); bsplit(b, hb, lb);
    hi = (uint32_t)reinterpret_cast<unsigned short&>(ha) |
         ((uint32_t)reinterpret_cast<unsigned short&>(hb) << 16);
    lo = (uint32_t)reinterpret_cast<unsigned short&>(la) |
         ((uint32_t)reinterpret_cast<unsigned short&>(lb) << 16);
}
__device__ __forceinline__ void ldsm4(uint32_t a[4], uint32_t addr) {
    asm volatile("ldmatrix.sync.aligned.m8n8.x4.shared.b16 {%0,%1,%2,%3}, [%4];"
                 : "=r"(a[0]), "=r"(a[1]), "=r"(a[2]), "=r"(a[3]) : "r"(addr));
}
__device__ __forceinline__ void mmabf(float c[4], const uint32_t a[4], uint32_t b0, uint32_t b1) {
    asm volatile(
        "mma.sync.aligned.m16n8k16.row.col.f32.bf16.bf16.f32 "
        "{%0,%1,%2,%3}, {%4,%5,%6,%7}, {%8,%9}, {%0,%1,%2,%3};"
        : "+f"(c[0]), "+f"(c[1]), "+f"(c[2]), "+f"(c[3])
        : "r"(a[0]), "r"(a[1]), "r"(a[2]), "r"(a[3]), "r"(b0), "r"(b1));
}

// ---------------- prep: write weights in mma-fragment lane order ----------------
// within a 32KB tile (128n x 128k): u32 index i = (ntg<<9)|(kq<<7)|(l<<2)|r
// value = bf16x2 { W[k][n], W[k+1][n] },  k = kq*32 + (r>>1)*16 + (r&1)*8 + 2*(l&3),
//                                         n = ntg*8 + (l>>2)
__global__ void __launch_bounds__(256) prep_kernel(const float* __restrict__ W1,
                                                   const float* __restrict__ W2,
                                                   const float* __restrict__ W3) {
    int stride = gridDim.x * blockDim.x;
    for (int p = blockIdx.x * blockDim.x + threadIdx.x; p < 57344; p += stride) {
        int pair = p >> 13, i = p & 8191;
        const float* W; int N, kb, nb; uint32_t base;
        if (pair == 0)      { W = W1; N = 128; kb = 0;   nb = 0; base = 0; }
        else if (pair == 1) { W = W1; N = 128; kb = 128; nb = 0; base = 65536; }
        else if (pair == 2) { W = W2; N = 128; kb = 0;   nb = 0; base = 131072; }
        else { int nc = pair - 3; W = W3; N = 512; kb = 0; nb = nc * 128;
               base = 196608 + (uint32_t)nc * 65536; }
        int ntg = i >> 9, kq = (i >> 7) & 3, l = (i >> 2) & 31, r = i & 3;
        int kl = kq * 32 + ((r >> 1) << 4) + ((r & 1) << 3) + ((l & 3) << 1);
        int nl = ntg * 8 + (l >> 2);
        int kg = kb + kl, ng = nb + nl;
        float w0 = W[(size_t)kg * N + ng], w1 = W[(size_t)(kg + 1) * N + ng];
        uint32_t hi, lo;
        pk2hl(w0, w1, hi, lo);
        ((uint32_t*)(g_wsc + base))[i] = hi;
        ((uint32_t*)(g_wsc + base + 32768))[i] = lo;
    }
}

// one 128x128-K GEMM tile: warp (wm,wn) does rows wm*32+rg*16, cols wn*32+q*8
__device__ __forceinline__ void gemm_tile(float acc[2][4][4],
        uint32_t aHb, uint32_t aLb, const uint4* __restrict__ fH,
        const uint4* __restrict__ fL, int wm, int wn, int lane)
{
    const int arow = wm * 32 + (lane & 15);
    const int akb = (lane >> 4) * 16;
    #pragma unroll
    for (int kq = 0; kq < 4; kq++) {
        uint4 bh[4], bl[4];
        #pragma unroll
        for (int q = 0; q < 4; q++) {
            int ntg = wn * 4 + q;
            bh[q] = __ldg(&fH[(ntg * 4 + kq) * 32 + lane]);
            bl[q] = __ldg(&fL[(ntg * 4 + kq) * 32 + lane]);
        }
        #pragma unroll
        for (int s = 0; s < 2; s++) {
            uint32_t aH[2][4], aL[2][4];
            #pragma unroll
            for (int rg = 0; rg < 2; rg++) {
                uint32_t off = (uint32_t)(arow + rg * 16) * ASTR + akb + kq * 64 + s * 32;
                ldsm4(aH[rg], aHb + off);
                ldsm4(aL[rg], aLb + off);
            }
            #pragma unroll
            for (int pass = 0; pass < 3; pass++)
                #pragma unroll
                for (int q = 0; q < 4; q++) {
                    uint32_t B0, B1;
                    if (pass == 2) { B0 = s ? bl[q].z : bl[q].x; B1 = s ? bl[q].w : bl[q].y; }
                    else           { B0 = s ? bh[q].z : bh[q].x; B1 = s ? bh[q].w : bh[q].y; }
                    #pragma unroll
                    for (int rg = 0; rg < 2; rg++)
                        mmabf(acc[rg][q], (pass == 1) ? aL[rg] : aH[rg], B0, B1);
                }
        }
    }
}

__global__ void __launch_bounds__(NT, 1) handnet_mma(
    const float* __restrict__ x,
    const float* __restrict__ A1, const float* __restrict__ A2, const float* __restrict__ A3,
    const float* __restrict__ b1, const float* __restrict__ b2, const float* __restrict__ b3,
    const float* __restrict__ fcW, const float* __restrict__ fcb,
    float* __restrict__ x3o, float* __restrict__ fco, int R)
{
    extern __shared__ char dyn[];
    __shared__ float sA[3 * 441];
    __shared__ float sb1[128], sb2[128], sb3[512], sfw[1536], sfb[3];
    __shared__ float OutP[128][12];

    const int tid = threadIdx.x, wid = tid >> 5, lane = tid & 31;
    const int wm = wid & 3, wn = wid >> 2;
    const uint32_t sb = su32(dyn);
    const int b0row = blockIdx.x * 126;
    const int RV = min(126, R - b0row);
    float* G = (float*)(dyn + GO);

    for (int i = tid; i < 441; i += NT) {
        sA[i] = A1[i]; sA[441 + i] = A2[i]; sA[882 + i] = A3[i];
    }
    if (tid < 128) { sb1[tid] = b1[tid]; sb2[tid] = b2[tid]; }
    if (tid < 512) sb3[tid] = b3[tid];
    for (int i = tid; i < 1536; i += NT) sfw[i] = fcW[i];
    if (tid < 3) sfb[tid] = fcb[tid];

    // ---- stage X (both K-chunks) as bf16 hi/lo, zero-padded to 128 rows ----
    for (int idx = tid; idx < 8192; idx += NT) {
        int r = idx >> 6, c4 = idx & 63;
        float4 v = make_float4(0.f, 0.f, 0.f, 0.f);
        if (r < RV) v = *(const float4*)(x + (size_t)(b0row + r) * 256 + c4 * 4);
        uint32_t h0, l0, h1, l1;
        pk2hl(v.x, v.y, h0, l0);
        pk2hl(v.z, v.w, h1, l1);
        int kc = c4 >> 5, cc = c4 & 31;
        uint32_t off = (uint32_t)r * ASTR + cc * 8;
        char* hb = dyn + (kc ? AH1 : AH0);
        char* lb = dyn + (kc ? AL1 : AL0);
        *(uint2*)(hb + off) = make_uint2(h0, h1);
        *(uint2*)(lb + off) = make_uint2(l0, l1);
    }
    __syncthreads();

    float acc[2][4][4];
    #pragma unroll
    for (int rg = 0; rg < 2; rg++)
        #pragma unroll
        for (int q = 0; q < 4; q++)
            #pragma unroll
            for (int c = 0; c < 4; c++) acc[rg][q][c] = 0.f;

    // ================= layer 1: K=256 = two fragment tiles =================
    gemm_tile(acc, sb + AH0, sb + AL0, (const uint4*)(g_wsc),
              (const uint4*)(g_wsc + 32768), wm, wn, lane);
    gemm_tile(acc, sb + AH1, sb + AL1, (const uint4*)(g_wsc + 65536),
              (const uint4*)(g_wsc + 98304), wm, wn, lane);

    for (int layer = 0; layer < 2; layer++) {
        // ---- dump acc -> G ----
        #pragma unroll
        for (int rg = 0; rg < 2; rg++) {
            int rA = wm * 32 + rg * 16 + (lane >> 2);
            #pragma unroll
            for (int q = 0; q < 4; q++) {
                int col = wn * 32 + q * 8 + 2 * (lane & 3);
                *(float2*)&G[rA * GSTR + col] = make_float2(acc[rg][q][0], acc[rg][q][1]);
                *(float2*)&G[(rA + 8) * GSTR + col] = make_float2(acc[rg][q][2], acc[rg][q][3]);
            }
        }
        __syncthreads();
        // ---- mix: layer0: A1+b1+relu ; layer1: A2+b2+relu then A3 ----
        {
            int c = tid & 127, half = tid >> 7;        // half 0..3
            const float* Aa = (layer == 0) ? sA : sA + 441;
            const float* Ab = (layer == 0) ? nullptr : sA + 882;
            float bias = (layer == 0) ? sb1[c] : sb2[c];
            for (int pass = 0; pass < 2; pass++) {
                int e = half + 4 * pass;
                if (e >= 6) break;
                bool valid = (e * 21 < RV);
                float v[21], t1[21];
                #pragma unroll
                for (int m = 0; m < 21; m++)
                    v[m] = valid ? G[(e * 21 + m) * GSTR + c] : 0.f;
                #pragma unroll
                for (int n = 0; n < 21; n++) {
                    float h = bias;
                    #pragma unroll
                    for (int m = 0; m < 21; m++) h = fmaf(Aa[n * 21 + m], v[m], h);
                    t1[n] = fmaxf(h, 0.f);
                }
                if (Ab) {
                    #pragma unroll
                    for (int n = 0; n < 21; n++) {
                        float h = 0.f;
                        #pragma unroll
                        for (int m = 0; m < 21; m++) h = fmaf(Ab[n * 21 + m], t1[m], h);
                        v[n] = h;
                    }
                } else {
                    #pragma unroll
                    for (int n = 0; n < 21; n++) v[n] = t1[n];
                }
                #pragma unroll
                for (int n = 0; n < 21; n++) {
                    int r = e * 21 + n;
                    float val = valid ? v[n] : 0.f;
                    __nv_bfloat16 h16, l16;
                    bsplit(val, h16, l16);
                    *(__nv_bfloat16*)(dyn + AH0 + r * ASTR + c * 2) = h16;
                    *(__nv_bfloat16*)(dyn + AL0 + r * ASTR + c * 2) = l16;
                }
            }
            if (half >= 2) {   // keep pad rows 126/127 zero
                int r = 126 + (half - 2);
                *(__nv_bfloat16*)(dyn + AH0 + r * ASTR + c * 2) = __float2bfloat16(0.f);
                *(__nv_bfloat16*)(dyn + AL0 + r * ASTR + c * 2) = __float2bfloat16(0.f);
            }
        }
        __syncthreads();
        if (layer == 0) {   // layer 2 GEMM
            #pragma unroll
            for (int rg = 0; rg < 2; rg++)
                #pragma unroll
                for (int q = 0; q < 4; q++)
                    #pragma unroll
                    for (int c = 0; c < 4; c++) acc[rg][q][c] = 0.f;
            gemm_tile(acc, sb + AH0, sb + AL0, (const uint4*)(g_wsc + 131072),
                      (const uint4*)(g_wsc + 163840), wm, wn, lane);
        }
    }

    // ================= layer 3: N=512 in 4 chunks + fused epilogue =================
    float p[4][3];
    #pragma unroll
    for (int i = 0; i < 4; i++)
        #pragma unroll
        for (int j = 0; j < 3; j++) p[i][j] = 0.f;

    for (int nc = 0; nc < 4; nc++) {
        #pragma unroll
        for (int rg = 0; rg < 2; rg++)
            #pragma unroll
            for (int q = 0; q < 4; q++)
                #pragma unroll
                for (int c = 0; c < 4; c++) acc[rg][q][c] = 0.f;
        gemm_tile(acc, sb + AH0, sb + AL0,
                  (const uint4*)(g_wsc + 196608 + (uint32_t)nc * 65536),
                  (const uint4*)(g_wsc + 196608 + (uint32_t)nc * 65536 + 32768),
                  wm, wn, lane);
        int colb = nc * 128 + wn * 32;
        #pragma unroll
        for (int rg = 0; rg < 2; rg++) {
            int rA = wm * 32 + rg * 16 + (lane >> 2), rB = rA + 8;
            bool vA = rA < RV, vB = rB < RV;
            #pragma unroll
            for (int q = 0; q < 4; q++) {
                int col = colb + q * 8 + 2 * (lane & 3);
                float v0 = fmaxf(acc[rg][q][0] + sb3[col], 0.f);
                float v1 = fmaxf(acc[rg][q][1] + sb3[col + 1], 0.f);
                float v2 = fmaxf(acc[rg][q][2] + sb3[col], 0.f);
                float v3 = fmaxf(acc[rg][q][3] + sb3[col + 1], 0.f);
                if (vA) *(float2*)&x3o[(size_t)(b0row + rA) * 512 + col] = make_float2(v0, v1);
                if (vB) *(float2*)&x3o[(size_t)(b0row + rB) * 512 + col] = make_float2(v2, v3);
                #pragma unroll
                for (int j = 0; j < 3; j++) {
                    p[rg * 2 + 0][j] = fmaf(v0, sfw[col * 3 + j],
                                        fmaf(v1, sfw[(col + 1) * 3 + j], p[rg * 2 + 0][j]));
                    p[rg * 2 + 1][j] = fmaf(v2, sfw[col * 3 + j],
                                        fmaf(v3, sfw[(col + 1) * 3 + j], p[rg * 2 + 1][j]));
                }
            }
        }
    }
    // quad reduce over lanes sharing the same row, then combine wn quarters via smem
    #pragma unroll
    for (int off = 1; off <= 2; off <<= 1)
        #pragma unroll
        for (int i = 0; i < 4; i++)
            #pragma unroll
            for (int j = 0; j < 3; j++)
                p[i][j] += __shfl_xor_sync(0xffffffffu, p[i][j], off);
    if ((lane & 3) == 0) {
        #pragma unroll
        for (int rg = 0; rg < 2; rg++) {
            int rA = wm * 32 + rg * 16 + (lane >> 2);
            #pragma unroll
            for (int j = 0; j < 3; j++) {
                OutP[rA][wn * 3 + j] = p[rg * 2 + 0][j];
                OutP[rA + 8][wn * 3 + j] = p[rg * 2 + 1][j];
            }
        }
    }
    __syncthreads();
    for (int t2 = tid; t2 < 378; t2 += NT) {
        int r = t2 / 3, j = t2 % 3;
        if (r < RV)
            fco[(size_t)(b0row + r) * 3 + j] =
                OutP[r][j] + OutP[r][3 + j] + OutP[r][6 + j] + OutP[r][9 + j] + sfb[j];
    }
}

extern "C" void kernel_launch(void* const* d_in, const int* in_sizes, int n_in,
                              void* d_out, int out_size)
{
    const float* x   = (const float*)d_in[0];
    const float* A1  = (const float*)d_in[1];
    const float* A2  = (const float*)d_in[2];
    const float* A3  = (const float*)d_in[3];
    const float* W1  = (const float*)d_in[4];
    const float* b1  = (const float*)d_in[5];
    const float* W2  = (const float*)d_in[6];
    const float* b2  = (const float*)d_in[7];
    const float* W3  = (const float*)d_in[8];
    const float* b3  = (const float*)d_in[9];
    const float* fcW = (const float*)d_in[10];
    const float* fcb = (const float*)d_in[11];

    const int B = in_sizes[0] / (21 * 256);
    const int R = B * 21;
    float* x3o = (float*)d_out;
    float* fco = x3o + (size_t)R * 512;

    cudaFuncSetAttribute(handnet_mma, cudaFuncAttributeMaxDynamicSharedMemorySize, DSMEM);
    prep_kernel<<<112, 256>>>(W1, W2, W3);
    handnet_mma<<<(R + 125) / 126, NT, DSMEM>>>(x, A1, A2, A3, b1, b2, b3,
                                                fcW, fcb, x3o, fco, R);
}

// round 15
// speedup vs baseline: 1.3240x; 1.3240x over previous
#include <cuda_runtime.h>
#include <cuda_fp16.h>
#include <cstddef>
#include <cstdint>

#define ASTR 272u
#define AC0 0u
#define AC1 34816u
#define GO  69632u
#define GSTR 132
#define DSMEM 137216
#define NT 512

// fragment-ordered fp16 weight tiles, 7 x 32KB:
// t0: W1 k0-127 @0 ; t1: W1 k128-255 @32768 ; t2: W2 @65536 ;
// t3-6: W3 n-chunk nc @98304+nc*32768
__device__ __align__(1024) unsigned char g_wsc[229376];

__device__ __forceinline__ uint32_t su32(const void* p) {
    uint32_t a;
    asm("{ .reg .u64 t; cvta.to.shared.u64 t, %1; cvt.u32.u64 %0, t; }" : "=r"(a) : "l"(p));
    return a;
}
__device__ __forceinline__ uint32_t pkh2(float a, float b) {
    __half2 h = __floats2half2_rn(a, b);
    return *reinterpret_cast<uint32_t*>(&h);
}
__device__ __forceinline__ void ldsm4(uint32_t a[4], uint32_t addr) {
    asm volatile("ldmatrix.sync.aligned.m8n8.x4.shared.b16 {%0,%1,%2,%3}, [%4];"
                 : "=r"(a[0]), "=r"(a[1]), "=r"(a[2]), "=r"(a[3]) : "r"(addr));
}
__device__ __forceinline__ void mmah(float c[4], const uint32_t a[4], uint32_t b0, uint32_t b1) {
    asm volatile(
        "mma.sync.aligned.m16n8k16.row.col.f32.f16.f16.f32 "
        "{%0,%1,%2,%3}, {%4,%5,%6,%7}, {%8,%9}, {%0,%1,%2,%3};"
        : "+f"(c[0]), "+f"(c[1]), "+f"(c[2]), "+f"(c[3])
        : "r"(a[0]), "r"(a[1]), "r"(a[2]), "r"(a[3]), "r"(b0), "r"(b1));
}

// ---------------- prep: write weights in mma-fragment lane order ----------------
// within a 32KB tile (128n x 128k): u32 index i = (ntg<<9)|(kq<<7)|(l<<2)|r
// value = fp16x2 { W[k][n], W[k+1][n] },  k = kq*32 + (r>>1)*16 + (r&1)*8 + 2*(l&3),
//                                         n = ntg*8 + (l>>2)
__global__ void __launch_bounds__(256) prep_kernel(const float* __restrict__ W1,
                                                   const float* __restrict__ W2,
                                                   const float* __restrict__ W3) {
    int stride = gridDim.x * blockDim.x;
    for (int p = blockIdx.x * blockDim.x + threadIdx.x; p < 57344; p += stride) {
        int tile = p >> 13, i = p & 8191;
        const float* W; int N, kb, nb;
        if (tile == 0)      { W = W1; N = 128; kb = 0;   nb = 0; }
        else if (tile == 1) { W = W1; N = 128; kb = 128; nb = 0; }
        else if (tile == 2) { W = W2; N = 128; kb = 0;   nb = 0; }
        else { W = W3; N = 512; kb = 0; nb = (tile - 3) * 128; }
        int ntg = i >> 9, kq = (i >> 7) & 3, l = (i >> 2) & 31, r = i & 3;
        int kl = kq * 32 + ((r >> 1) << 4) + ((r & 1) << 3) + ((l & 3) << 1);
        int nl = ntg * 8 + (l >> 2);
        int kg = kb + kl, ng = nb + nl;
        ((uint32_t*)g_wsc)[p] = pkh2(W[(size_t)kg * N + ng], W[(size_t)(kg + 1) * N + ng]);
    }
}

// one 128x128-K GEMM tile: warp (wm,wn) does rows wm*32+rg*16, cols wn*32+q*8
__device__ __forceinline__ void gemm_tile(float acc[2][4][4],
        uint32_t aB, const uint4* __restrict__ fW, int wm, int wn, int lane)
{
    const int arow = wm * 32 + (lane & 15);
    const int akb = (lane >> 4) * 16;
    #pragma unroll
    for (int kq = 0; kq < 4; kq++) {
        uint4 bh[4];
        #pragma unroll
        for (int q = 0; q < 4; q++)
            bh[q] = __ldg(&fW[((wn * 4 + q) * 4 + kq) * 32 + lane]);
        #pragma unroll
        for (int s = 0; s < 2; s++) {
            uint32_t aF[2][4];
            #pragma unroll
            for (int rg = 0; rg < 2; rg++)
                ldsm4(aF[rg], aB + (uint32_t)(arow + rg * 16) * ASTR + akb + kq * 64 + s * 32);
            #pragma unroll
            for (int q = 0; q < 4; q++) {
                uint32_t B0 = s ? bh[q].z : bh[q].x;
                uint32_t B1 = s ? bh[q].w : bh[q].y;
                #pragma unroll
                for (int rg = 0; rg < 2; rg++)
                    mmah(acc[rg][q], aF[rg], B0, B1);
            }
        }
    }
}

__global__ void __launch_bounds__(NT, 1) handnet_mma(
    const float* __restrict__ x,
    const float* __restrict__ A1, const float* __restrict__ A2, const float* __restrict__ A3,
    const float* __restrict__ b1, const float* __restrict__ b2, const float* __restrict__ b3,
    const float* __restrict__ fcW, const float* __restrict__ fcb,
    float* __restrict__ x3o, float* __restrict__ fco, int R)
{
    extern __shared__ char dyn[];
    __shared__ float sA[3 * 441];
    __shared__ float sb1[128], sb2[128], sb3[512], sfw[1536], sfb[3];
    __shared__ float OutP[128][12];

    const int tid = threadIdx.x, wid = tid >> 5, lane = tid & 31;
    const int wm = wid & 3, wn = wid >> 2;
    const uint32_t sb = su32(dyn);
    const int b0row = blockIdx.x * 126;
    const int RV = min(126, R - b0row);
    float* G = (float*)(dyn + GO);

    for (int i = tid; i < 441; i += NT) {
        sA[i] = A1[i]; sA[441 + i] = A2[i]; sA[882 + i] = A3[i];
    }
    if (tid < 128) { sb1[tid] = b1[tid]; sb2[tid] = b2[tid]; }
    if (tid < 512) sb3[tid] = b3[tid];
    for (int i = tid; i < 1536; i += NT) sfw[i] = fcW[i];
    if (tid < 3) sfb[tid] = fcb[tid];

    // ---- stage X (both K-chunks) as fp16, zero-padded to 128 rows ----
    for (int idx = tid; idx < 8192; idx += NT) {
        int r = idx >> 6, c4 = idx & 63;
        float4 v = make_float4(0.f, 0.f, 0.f, 0.f);
        if (r < RV) v = *(const float4*)(x + (size_t)(b0row + r) * 256 + c4 * 4);
        int kc = c4 >> 5, cc = c4 & 31;
        uint32_t off = (uint32_t)r * ASTR + cc * 8;
        *(uint2*)(dyn + (kc ? AC1 : AC0) + off) = make_uint2(pkh2(v.x, v.y), pkh2(v.z, v.w));
    }
    __syncthreads();

    float acc[2][4][4];
    #pragma unroll
    for (int rg = 0; rg < 2; rg++)
        #pragma unroll
        for (int q = 0; q < 4; q++)
            #pragma unroll
            for (int c = 0; c < 4; c++) acc[rg][q][c] = 0.f;

    // ================= layer 1: K=256 = two fragment tiles =================
    gemm_tile(acc, sb + AC0, (const uint4*)(g_wsc), wm, wn, lane);
    gemm_tile(acc, sb + AC1, (const uint4*)(g_wsc + 32768), wm, wn, lane);

    for (int layer = 0; layer < 2; layer++) {
        // ---- dump acc -> G ----
        #pragma unroll
        for (int rg = 0; rg < 2; rg++) {
            int rA = wm * 32 + rg * 16 + (lane >> 2);
            #pragma unroll
            for (int q = 0; q < 4; q++) {
                int col = wn * 32 + q * 8 + 2 * (lane & 3);
                *(float2*)&G[rA * GSTR + col] = make_float2(acc[rg][q][0], acc[rg][q][1]);
                *(float2*)&G[(rA + 8) * GSTR + col] = make_float2(acc[rg][q][2], acc[rg][q][3]);
            }
        }
        __syncthreads();
        // ---- mix: layer0: A1+b1+relu ; layer1: A2+b2+relu then A3 ----
        {
            int c = tid & 127, half = tid >> 7;        // half 0..3
            const float* Aa = (layer == 0) ? sA : sA + 441;
            const float* Ab = (layer == 0) ? nullptr : sA + 882;
            float bias = (layer == 0) ? sb1[c] : sb2[c];
            for (int pass = 0; pass < 2; pass++) {
                int e = half + 4 * pass;
                if (e >= 6) break;
                bool valid = (e * 21 < RV);
                float v[21], t1[21];
                #pragma unroll
                for (int m = 0; m < 21; m++)
                    v[m] = valid ? G[(e * 21 + m) * GSTR + c] : 0.f;
                #pragma unroll
                for (int n = 0; n < 21; n++) {
                    float h = bias;
                    #pragma unroll
                    for (int m = 0; m < 21; m++) h = fmaf(Aa[n * 21 + m], v[m], h);
                    t1[n] = fmaxf(h, 0.f);
                }
                if (Ab) {
                    #pragma unroll
                    for (int n = 0; n < 21; n++) {
                        float h = 0.f;
                        #pragma unroll
                        for (int m = 0; m < 21; m++) h = fmaf(Ab[n * 21 + m], t1[m], h);
                        v[n] = h;
                    }
                } else {
                    #pragma unroll
                    for (int n = 0; n < 21; n++) v[n] = t1[n];
                }
                #pragma unroll
                for (int n = 0; n < 21; n++) {
                    int r = e * 21 + n;
                    float val = valid ? v[n] : 0.f;
                    *(__half*)(dyn + AC0 + r * ASTR + c * 2) = __float2half_rn(val);
                }
            }
            if (half >= 2) {   // keep pad rows 126/127 zero
                int r = 126 + (half - 2);
                *(__half*)(dyn + AC0 + r * ASTR + c * 2) = __float2half_rn(0.f);
            }
        }
        __syncthreads();
        if (layer == 0) {   // layer 2 GEMM
            #pragma unroll
            for (int rg = 0; rg < 2; rg++)
                #pragma unroll
                for (int q = 0; q < 4; q++)
                    #pragma unroll
                    for (int c = 0; c < 4; c++) acc[rg][q][c] = 0.f;
            gemm_tile(acc, sb + AC0, (const uint4*)(g_wsc + 65536), wm, wn, lane);
        }
    }

    // ================= layer 3: N=512 in 4 chunks + fused epilogue =================
    float p[4][3];
    #pragma unroll
    for (int i = 0; i < 4; i++)
        #pragma unroll
        for (int j = 0; j < 3; j++) p[i][j] = 0.f;

    for (int nc = 0; nc < 4; nc++) {
        #pragma unroll
        for (int rg = 0; rg < 2; rg++)
            #pragma unroll
            for (int q = 0; q < 4; q++)
                #pragma unroll
                for (int c = 0; c < 4; c++) acc[rg][q][c] = 0.f;
        gemm_tile(acc, sb + AC0,
                  (const uint4*)(g_wsc + 98304 + (uint32_t)nc * 32768), wm, wn, lane);
        int colb = nc * 128 + wn * 32;
        #pragma unroll
        for (int rg = 0; rg < 2; rg++) {
            int rA = wm * 32 + rg * 16 + (lane >> 2), rB = rA + 8;
            bool vA = rA < RV, vB = rB < RV;
            #pragma unroll
            for (int q = 0; q < 4; q++) {
                int col = colb + q * 8 + 2 * (lane & 3);
                float v0 = fmaxf(acc[rg][q][0] + sb3[col], 0.f);
                float v1 = fmaxf(acc[rg][q][1] + sb3[col + 1], 0.f);
                float v2 = fmaxf(acc[rg][q][2] + sb3[col], 0.f);
                float v3 = fmaxf(acc[rg][q][3] + sb3[col + 1], 0.f);
                if (vA) *(float2*)&x3o[(size_t)(b0row + rA) * 512 + col] = make_float2(v0, v1);
                if (vB) *(float2*)&x3o[(size_t)(b0row + rB) * 512 + col] = make_float2(v2, v3);
                #pragma unroll
                for (int j = 0; j < 3; j++) {
                    p[rg * 2 + 0][j] = fmaf(v0, sfw[col * 3 + j],
                                        fmaf(v1, sfw[(col + 1) * 3 + j], p[rg * 2 + 0][j]));
                    p[rg * 2 + 1][j] = fmaf(v2, sfw[col * 3 + j],
                                        fmaf(v3, sfw[(col + 1) * 3 + j], p[rg * 2 + 1][j]));
                }
            }
        }
    }
    // quad reduce over lanes sharing the same row, then combine wn quarters via smem
    #pragma unroll
    for (int off = 1; off <= 2; off <<= 1)
        #pragma unroll
        for (int i = 0; i < 4; i++)
            #pragma unroll
            for (int j = 0; j < 3; j++)
                p[i][j] += __shfl_xor_sync(0xffffffffu, p[i][j], off);
    if ((lane & 3) == 0) {
        #pragma unroll
        for (int rg = 0; rg < 2; rg++) {
            int rA = wm * 32 + rg * 16 + (lane >> 2);
            #pragma unroll
            for (int j = 0; j < 3; j++) {
                OutP[rA][wn * 3 + j] = p[rg * 2 + 0][j];
                OutP[rA + 8][wn * 3 + j] = p[rg * 2 + 1][j];
            }
        }
    }
    __syncthreads();
    for (int t2 = tid; t2 < 378; t2 += NT) {
        int r = t2 / 3, j = t2 % 3;
        if (r < RV)
            fco[(size_t)(b0row + r) * 3 + j] =
                OutP[r][j] + OutP[r][3 + j] + OutP[r][6 + j] + OutP[r][9 + j] + sfb[j];
    }
}

extern "C" void kernel_launch(void* const* d_in, const int* in_sizes, int n_in,
                              void* d_out, int out_size)
{
    const float* x   = (const float*)d_in[0];
    const float* A1  = (const float*)d_in[1];
    const float* A2  = (const float*)d_in[2];
    const float* A3  = (const float*)d_in[3];
    const float* W1  = (const float*)d_in[4];
    const float* b1  = (const float*)d_in[5];
    const float* W2  = (const float*)d_in[6];
    const float* b2  = (const float*)d_in[7];
    const float* W3  = (const float*)d_in[8];
    const float* b3  = (const float*)d_in[9];
    const float* fcW = (const float*)d_in[10];
    const float* fcb = (const float*)d_in[11];

    const int B = in_sizes[0] / (21 * 256);
    const int R = B * 21;
    float* x3o = (float*)d_out;
    float* fco = x3o + (size_t)R * 512;

    cudaFuncSetAttribute(handnet_mma, cudaFuncAttributeMaxDynamicSharedMemorySize, DSMEM);
    prep_kernel<<<112, 256>>>(W1, W2, W3);
    handnet_mma<<<(R + 125) / 126, NT, DSMEM>>>(x, A1, A2, A3, b1, b2, b3,
                                                fcW, fcb, x3o, fco, R);
}

// round 16
// speedup vs baseline: 1.5181x; 1.1466x over previous
#include <cuda_runtime.h>
#include <cuda_fp16.h>
#include <cstddef>
#include <cstdint>

#define ASTR 272u
#define AC0 0u
#define AC1 34816u
#define GO  69632u
#define GSTR 132
#define DSMEM 137216
#define NT 512

// fragment-ordered fp16 weight tiles, 7 x 32KB:
// t0: W1 k0-127 @0 ; t1: W1 k128-255 @32768 ; t2: W2 @65536 ;
// t3-6: W3 n-chunk nc @98304+nc*32768
__device__ __align__(1024) unsigned char g_wsc[229376];
// sparse A rows: (lay*21+n)*4 + s -> {v0, byteoff0_bits, v1, byteoff1_bits}, 8 slots/row
__device__ __align__(16) float4 g_spk[252];

__device__ __forceinline__ uint32_t su32(const void* p) {
    uint32_t a;
    asm("{ .reg .u64 t; cvta.to.shared.u64 t, %1; cvt.u32.u64 %0, t; }" : "=r"(a) : "l"(p));
    return a;
}
__device__ __forceinline__ uint32_t pkh2(float a, float b) {
    __half2 h = __floats2half2_rn(a, b);
    return *reinterpret_cast<uint32_t*>(&h);
}
__device__ __forceinline__ void ldsm4(uint32_t a[4], uint32_t addr) {
    asm volatile("ldmatrix.sync.aligned.m8n8.x4.shared.b16 {%0,%1,%2,%3}, [%4];"
                 : "=r"(a[0]), "=r"(a[1]), "=r"(a[2]), "=r"(a[3]) : "r"(addr));
}
__device__ __forceinline__ void mmah(float c[4], const uint32_t a[4], uint32_t b0, uint32_t b1) {
    asm volatile(
        "mma.sync.aligned.m16n8k16.row.col.f32.f16.f16.f32 "
        "{%0,%1,%2,%3}, {%4,%5,%6,%7}, {%8,%9}, {%0,%1,%2,%3};"
        : "+f"(c[0]), "+f"(c[1]), "+f"(c[2]), "+f"(c[3])
        : "r"(a[0]), "r"(a[1]), "r"(a[2]), "r"(a[3]), "r"(b0), "r"(b1));
}

// ---------------- prep: fragment-order weights + sparse A rows ----------------
__global__ void __launch_bounds__(256) prep_kernel(const float* __restrict__ W1,
                                                   const float* __restrict__ W2,
                                                   const float* __restrict__ W3,
                                                   const float* __restrict__ A1,
                                                   const float* __restrict__ A2,
                                                   const float* __restrict__ A3) {
    if (blockIdx.x == 0 && threadIdx.x < 63) {        // sparse A build
        int lay = threadIdx.x / 21, n = threadIdx.x % 21;
        const float* A = (lay == 0) ? A1 : (lay == 1) ? A2 : A3;
        float v[8]; int ix[8]; int cnt = 0;
        for (int m = 0; m < 21; m++) {
            float a = A[n * 21 + m];
            if (a != 0.f && cnt < 8) { v[cnt] = a; ix[cnt] = m; cnt++; }
        }
        for (; cnt < 8; cnt++) { v[cnt] = 0.f; ix[cnt] = 0; }
        #pragma unroll
        for (int s = 0; s < 4; s++)
            g_spk[(lay * 21 + n) * 4 + s] =
                make_float4(v[2 * s],     __int_as_float(ix[2 * s] * (GSTR * 4)),
                            v[2 * s + 1], __int_as_float(ix[2 * s + 1] * (GSTR * 4)));
    }
    int stride = gridDim.x * blockDim.x;
    for (int p = blockIdx.x * blockDim.x + threadIdx.x; p < 57344; p += stride) {
        int tile = p >> 13, i = p & 8191;
        const float* W; int N, kb, nb;
        if (tile == 0)      { W = W1; N = 128; kb = 0;   nb = 0; }
        else if (tile == 1) { W = W1; N = 128; kb = 128; nb = 0; }
        else if (tile == 2) { W = W2; N = 128; kb = 0;   nb = 0; }
        else { W = W3; N = 512; kb = 0; nb = (tile - 3) * 128; }
        int ntg = i >> 9, kq = (i >> 7) & 3, l = (i >> 2) & 31, r = i & 3;
        int kl = kq * 32 + ((r >> 1) << 4) + ((r & 1) << 3) + ((l & 3) << 1);
        int nl = ntg * 8 + (l >> 2);
        int kg = kb + kl, ng = nb + nl;
        ((uint32_t*)g_wsc)[p] = pkh2(W[(size_t)kg * N + ng], W[(size_t)(kg + 1) * N + ng]);
    }
}

// one 128x128-K GEMM tile: warp (wm,wn) does rows wm*32+rg*16, cols wn*32+q*8
__device__ __forceinline__ void gemm_tile(float acc[2][4][4],
        uint32_t aB, const uint4* __restrict__ fW, int wm, int wn, int lane)
{
    const int arow = wm * 32 + (lane & 15);
    const int akb = (lane >> 4) * 16;
    #pragma unroll
    for (int kq = 0; kq < 4; kq++) {
        uint4 bh[4];
        #pragma unroll
        for (int q = 0; q < 4; q++)
            bh[q] = __ldg(&fW[((wn * 4 + q) * 4 + kq) * 32 + lane]);
        #pragma unroll
        for (int s = 0; s < 2; s++) {
            uint32_t aF[2][4];
            #pragma unroll
            for (int rg = 0; rg < 2; rg++)
                ldsm4(aF[rg], aB + (uint32_t)(arow + rg * 16) * ASTR + akb + kq * 64 + s * 32);
            #pragma unroll
            for (int q = 0; q < 4; q++) {
                uint32_t B0 = s ? bh[q].z : bh[q].x;
                uint32_t B1 = s ? bh[q].w : bh[q].y;
                #pragma unroll
                for (int rg = 0; rg < 2; rg++)
                    mmah(acc[rg][q], aF[rg], B0, B1);
            }
        }
    }
}

// sparse 21-row matvec on this thread's column: out[n] = bias? + sum sparse(A row n) * Gc
__device__ __forceinline__ float sp_row(const float4* __restrict__ pk, const char* Gc, float init) {
    float h = init;
    #pragma unroll
    for (int s = 0; s < 4; s++) {
        float4 p = pk[s];
        h = fmaf(p.x, *(const float*)(Gc + __float_as_int(p.y)), h);
        h = fmaf(p.z, *(const float*)(Gc + __float_as_int(p.w)), h);
    }
    return h;
}

__global__ void __launch_bounds__(NT, 1) handnet_mma(
    const float* __restrict__ x,
    const float* __restrict__ b1, const float* __restrict__ b2, const float* __restrict__ b3,
    const float* __restrict__ fcW, const float* __restrict__ fcb,
    float* __restrict__ x3o, float* __restrict__ fco, int R)
{
    extern __shared__ char dyn[];
    __shared__ float4 sPk[252];
    __shared__ float sb1[128], sb2[128], sb3[512], sfw[1536], sfb[3];
    __shared__ float OutP[128][12];

    const int tid = threadIdx.x, wid = tid >> 5, lane = tid & 31;
    const int wm = wid & 3, wn = wid >> 2;
    const uint32_t sb = su32(dyn);
    const int b0row = blockIdx.x * 126;
    const int RV = min(126, R - b0row);
    float* G = (float*)(dyn + GO);

    if (tid < 252) sPk[tid] = g_spk[tid];
    if (tid < 128) { sb1[tid] = b1[tid]; sb2[tid] = b2[tid]; }
    if (tid < 512) sb3[tid] = b3[tid];
    for (int i = tid; i < 1536; i += NT) sfw[i] = fcW[i];
    if (tid < 3) sfb[tid] = fcb[tid];

    // ---- stage X (both K-chunks) as fp16, zero-padded to 128 rows ----
    for (int idx = tid; idx < 8192; idx += NT) {
        int r = idx >> 6, c4 = idx & 63;
        float4 v = make_float4(0.f, 0.f, 0.f, 0.f);
        if (r < RV) v = *(const float4*)(x + (size_t)(b0row + r) * 256 + c4 * 4);
        int kc = c4 >> 5, cc = c4 & 31;
        uint32_t off = (uint32_t)r * ASTR + cc * 8;
        *(uint2*)(dyn + (kc ? AC1 : AC0) + off) = make_uint2(pkh2(v.x, v.y), pkh2(v.z, v.w));
    }
    __syncthreads();

    float acc[2][4][4];
    #pragma unroll
    for (int rg = 0; rg < 2; rg++)
        #pragma unroll
        for (int q = 0; q < 4; q++)
            #pragma unroll
            for (int c = 0; c < 4; c++) acc[rg][q][c] = 0.f;

    // ================= layer 1: K=256 = two fragment tiles =================
    gemm_tile(acc, sb + AC0, (const uint4*)(g_wsc), wm, wn, lane);
    gemm_tile(acc, sb + AC1, (const uint4*)(g_wsc + 32768), wm, wn, lane);

    for (int layer = 0; layer < 2; layer++) {
        // ---- dump acc -> G ----
        #pragma unroll
        for (int rg = 0; rg < 2; rg++) {
            int rA = wm * 32 + rg * 16 + (lane >> 2);
            #pragma unroll
            for (int q = 0; q < 4; q++) {
                int col = wn * 32 + q * 8 + 2 * (lane & 3);
                *(float2*)&G[rA * GSTR + col] = make_float2(acc[rg][q][0], acc[rg][q][1]);
                *(float2*)&G[(rA + 8) * GSTR + col] = make_float2(acc[rg][q][2], acc[rg][q][3]);
            }
        }
        __syncthreads();
        // ---- sparse mix: layer0: A1+b1+relu ; layer1: A2+b2+relu then A3 ----
        {
            int c = tid & 127, half = tid >> 7;        // half 0..3
            float bias = (layer == 0) ? sb1[c] : sb2[c];
            const float4* pkA = &sPk[(layer == 0 ? 0 : 21) * 4];
            for (int pass = 0; pass < 2; pass++) {
                int e = half + 4 * pass;
                if (e >= 6) break;
                bool valid = (e * 21 < RV);
                float* Gc = G + e * 21 * GSTR + c;
                const char* Gcb = (const char*)Gc;
                float out[21];
                #pragma unroll
                for (int n = 0; n < 21; n++)
                    out[n] = fmaxf(sp_row(pkA + n * 4, Gcb, bias), 0.f);
                if (layer == 1) {
                    #pragma unroll
                    for (int n = 0; n < 21; n++) Gc[n * GSTR] = out[n];
                    const float4* pk3 = &sPk[42 * 4];
                    #pragma unroll
                    for (int n = 0; n < 21; n++)
                        out[n] = sp_row(pk3 + n * 4, Gcb, 0.f);
                }
                #pragma unroll
                for (int n = 0; n < 21; n++) {
                    int r = e * 21 + n;
                    *(__half*)(dyn + AC0 + r * ASTR + c * 2) =
                        __float2half_rn(valid ? out[n] : 0.f);
                }
            }
            if (half >= 2) {   // keep pad rows 126/127 zero
                int r = 126 + (half - 2);
                *(__half*)(dyn + AC0 + r * ASTR + c * 2) = __float2half_rn(0.f);
            }
        }
        __syncthreads();
        if (layer == 0) {   // layer 2 GEMM
            #pragma unroll
            for (int rg = 0; rg < 2; rg++)
                #pragma unroll
                for (int q = 0; q < 4; q++)
                    #pragma unroll
                    for (int c = 0; c < 4; c++) acc[rg][q][c] = 0.f;
            gemm_tile(acc, sb + AC0, (const uint4*)(g_wsc + 65536), wm, wn, lane);
        }
    }

    // ================= layer 3: N=512 in 4 chunks + fused epilogue =================
    float p[4][3];
    #pragma unroll
    for (int i = 0; i < 4; i++)
        #pragma unroll
        for (int j = 0; j < 3; j++) p[i][j] = 0.f;

    for (int nc = 0; nc < 4; nc++) {
        #pragma unroll
        for (int rg = 0; rg < 2; rg++)
            #pragma unroll
            for (int q = 0; q < 4; q++)
                #pragma unroll
                for (int c = 0; c < 4; c++) acc[rg][q][c] = 0.f;
        gemm_tile(acc, sb + AC0,
                  (const uint4*)(g_wsc + 98304 + (uint32_t)nc * 32768), wm, wn, lane);
        int colb = nc * 128 + wn * 32;
        #pragma unroll
        for (int rg = 0; rg < 2; rg++) {
            int rA = wm * 32 + rg * 16 + (lane >> 2), rB = rA + 8;
            bool vA = rA < RV, vB = rB < RV;
            #pragma unroll
            for (int q = 0; q < 4; q++) {
                int col = colb + q * 8 + 2 * (lane & 3);
                float v0 = fmaxf(acc[rg][q][0] + sb3[col], 0.f);
                float v1 = fmaxf(acc[rg][q][1] + sb3[col + 1], 0.f);
                float v2 = fmaxf(acc[rg][q][2] + sb3[col], 0.f);
                float v3 = fmaxf(acc[rg][q][3] + sb3[col + 1], 0.f);
                if (vA) *(float2*)&x3o[(size_t)(b0row + rA) * 512 + col] = make_float2(v0, v1);
                if (vB) *(float2*)&x3o[(size_t)(b0row + rB) * 512 + col] = make_float2(v2, v3);
                #pragma unroll
                for (int j = 0; j < 3; j++) {
                    p[rg * 2 + 0][j] = fmaf(v0, sfw[col * 3 + j],
                                        fmaf(v1, sfw[(col + 1) * 3 + j], p[rg * 2 + 0][j]));
                    p[rg * 2 + 1][j] = fmaf(v2, sfw[col * 3 + j],
                                        fmaf(v3, sfw[(col + 1) * 3 + j], p[rg * 2 + 1][j]));
                }
            }
        }
    }
    // quad reduce over lanes sharing the same row, then combine wn quarters via smem
    #pragma unroll
    for (int off = 1; off <= 2; off <<= 1)
        #pragma unroll
        for (int i = 0; i < 4; i++)
            #pragma unroll
            for (int j = 0; j < 3; j++)
                p[i][j] += __shfl_xor_sync(0xffffffffu, p[i][j], off);
    if ((lane & 3) == 0) {
        #pragma unroll
        for (int rg = 0; rg < 2; rg++) {
            int rA = wm * 32 + rg * 16 + (lane >> 2);
            #pragma unroll
            for (int j = 0; j < 3; j++) {
                OutP[rA][wn * 3 + j] = p[rg * 2 + 0][j];
                OutP[rA + 8][wn * 3 + j] = p[rg * 2 + 1][j];
            }
        }
    }
    __syncthreads();
    for (int t2 = tid; t2 < 378; t2 += NT) {
        int r = t2 / 3, j = t2 % 3;
        if (r < RV)
            fco[(size_t)(b0row + r) * 3 + j] =
                OutP[r][j] + OutP[r][3 + j] + OutP[r][6 + j] + OutP[r][9 + j] + sfb[j];
    }
}

extern "C" void kernel_launch(void* const* d_in, const int* in_sizes, int n_in,
                              void* d_out, int out_size)
{
    const float* x   = (const float*)d_in[0];
    const float* A1  = (const float*)d_in[1];
    const float* A2  = (const float*)d_in[2];
    const float* A3  = (const float*)d_in[3];
    const float* W1  = (const float*)d_in[4];
    const float* b1  = (const float*)d_in[5];
    const float* W2  = (const float*)d_in[6];
    const float* b2  = (const float*)d_in[7];
    const float* W3  = (const float*)d_in[8];
    const float* b3  = (const float*)d_in[9];
    const float* fcW = (const float*)d_in[10];
    const float* fcb = (const float*)d_in[11];

    const int B = in_sizes[0] / (21 * 256);
    const int R = B * 21;
    float* x3o = (float*)d_out;
    float* fco = x3o + (size_t)R * 512;

    cudaFuncSetAttribute(handnet_mma, cudaFuncAttributeMaxDynamicSharedMemorySize, DSMEM);
    prep_kernel<<<112, 256>>>(W1, W2, W3, A1, A2, A3);
    handnet_mma<<<(R + 125) / 126, NT, DSMEM>>>(x, b1, b2, b3,
                                                fcW, fcb, x3o, fco, R);
}